// round 16
// baseline (speedup 1.0000x reference)
#include <cuda_runtime.h>
#include <cuda_bf16.h>
#include <math.h>

// ---- problem constants ----
#define A_DIM 56
#define E_DIM 128
#define LAMBDA_INIT 0.7f
#define LN_EPS 1e-5f
#define SCALING 0.25f   // HD^-0.5, HD=16

// ---- repacked weight sizes (32-bit words, each = bf16x2) ----
#define K1_STEPS 25               // conv1: K = 400 (49 octets + 1 zero octet), /16
#define K2_STEPS 56               // conv2: K = 7*128=896, /16
#define K3_STEPS 8                // kproj: K=128, /16
#define W1_WORDS (2 * K1_STEPS * 256)
#define W2_WORDS (4 * K2_STEPS * 256)
#define W3_WORDS (4 * K3_STEPS * 256)
#define W_TOTAL  (W1_WORDS + W2_WORDS + W3_WORDS)

__device__ __align__(16) unsigned g_w1[W1_WORDS];
__device__ __align__(16) unsigned g_w2[W2_WORDS];
__device__ __align__(16) unsigned g_w3[W3_WORDS];

// ---- smem layout (32-bit words), TWO batches per CTA, 2 CTAs/SM ----
#define SXE_B   4608
#define SXB_B   4352
#define SH1B_B  4608
#define SK_B    8448
#define SK_STRIDE 132

#define OFF_SXE   0
#define OFF_SXB   9216
#define OFF_SH1B  17920
#define OFF_SK    9216            // overlay SXB+SH1B
#define OFF_SQ    27136           // [2][128] f32
#define OFF_SC    27392
#define OFF_SQN   0               // overlay SXE (dead after kproj)
#define OFF_SA    256
#define OFF_SA2   1216
#define SMEM_WORDS 27396          // 109584 B -> 2 CTAs/SM

__device__ __forceinline__ float silu_f(float v) {
    return v / (1.0f + __expf(-v));
}
__device__ __forceinline__ unsigned pack_bf2(float lo, float hi) {
    unsigned u;
    asm("cvt.rn.bf16x2.f32 %0, %1, %2;" : "=r"(u) : "f"(hi), "f"(lo));
    return u;
}
__device__ __forceinline__ void mma_bf16(float* d, const unsigned* a, const unsigned* b) {
    asm volatile(
        "mma.sync.aligned.m16n8k16.row.col.f32.bf16.bf16.f32 "
        "{%0,%1,%2,%3}, {%4,%5,%6,%7}, {%8,%9}, {%0,%1,%2,%3};"
        : "+f"(d[0]), "+f"(d[1]), "+f"(d[2]), "+f"(d[3])
        : "r"(a[0]), "r"(a[1]), "r"(a[2]), "r"(a[3]), "r"(b[0]), "r"(b[1]));
}

// ================== weight repack: fragment-order bf16x2, LDG.128-friendly ==================
// word idx per m-group block = ks*256 + h*128 + lane*4 + jj ; j = h*4 + jj (a-reg index),
// r = j&3; row = mg*32 + (j>>2)*16 + g + (r&1)*8 ; kk0 = ks*16 + 2*tg + (r>=2)*8.
// conv1: OCTET-major k: kk -> o=kk>>3, w=kk&7; ia=(o%7)*8+w, dk=o/7; valid o<49
// conv2: tap-major: kk -> dk=kk>>7, ie=kk&127
// kproj: kk = e
__global__ void __launch_bounds__(256)
repack_kernel(const float* __restrict__ w_emb,
              const float* __restrict__ w_atlas,
              const float* __restrict__ w_k)
{
    int i = blockIdx.x * 256 + threadIdx.x;
    if (i >= W_TOTAL) return;

    const float* src;
    unsigned* dst;
    int K, src_stride, row_lim, ii, which;
    if (i < W1_WORDS) {
        ii = i; src = w_emb; dst = g_w1; K = K1_STEPS; src_stride = 392; row_lim = 56; which = 1;
    } else if (i < W1_WORDS + W2_WORDS) {
        ii = i - W1_WORDS; src = w_atlas; dst = g_w2; K = K2_STEPS; src_stride = 896; row_lim = 128; which = 2;
    } else {
        ii = i - W1_WORDS - W2_WORDS; src = w_k; dst = g_w3; K = K3_STEPS; src_stride = 128; row_lim = 128; which = 3;
    }
    int jj   = ii & 3;
    int lane = (ii >> 2) & 31;
    int h    = (ii >> 7) & 1;
    int blk  = ii >> 8;
    int ks   = blk % K;
    int mg   = blk / K;
    int j    = h * 4 + jj;
    int r    = j & 3;
    int g = lane >> 2, tg = lane & 3;
    int row = mg * 32 + (j >> 2) * 16 + g + ((r & 1) ? 8 : 0);
    int kk0 = ks * 16 + 2 * tg + ((r >= 2) ? 8 : 0);

    float v[2] = {0.f, 0.f};
    if (row < row_lim) {
        #pragma unroll
        for (int c = 0; c < 2; ++c) {
            int kk = kk0 + c;
            int col = -1;
            if (which == 1) {
                int o = kk >> 3, w = kk & 7;
                if (o < 49) {
                    int ia = (o % 7) * 8 + w, dk = o / 7;
                    col = ia * 7 + dk;
                }
            } else if (which == 2) {
                int dk = kk >> 7, ie = kk & 127;
                col = ie * 7 + dk;
            } else {
                col = kk;
            }
            if (col >= 0) v[c] = src[row * src_stride + col];
        }
    }
    dst[ii] = pack_bf2(v[0], v[1]);
}

extern __shared__ unsigned smw[];

__global__ void __launch_bounds__(256, 2)
atlas_mdattn_tc(
    const float* __restrict__ x,       // [B,56,128]
    const float* __restrict__ b_emb,   // [56]
    const float* __restrict__ b_atlas, // [128]
    const float* __restrict__ qn_w, const float* __restrict__ qn_b,
    const float* __restrict__ kn_w, const float* __restrict__ kn_b,
    const float* __restrict__ lq1, const float* __restrict__ lk1,
    const float* __restrict__ lq2, const float* __restrict__ lk2,
    float* __restrict__ out)           // [B,56]
{
    const int t = threadIdx.x;
    const int lane = t & 31, wid = t >> 5;
    const int g = lane >> 2, tg = lane & 3;

    unsigned* SXE  = smw + OFF_SXE;
    unsigned* SXB  = smw + OFF_SXB;
    unsigned* SH1B = smw + OFF_SH1B;
    float* SK  = (float*)(smw + OFF_SK);
    float* Sq  = (float*)(smw + OFF_SQ);
    float* Sqn = (float*)(smw + OFF_SQN);
    float* SA  = (float*)(smw + OFF_SA);
    float* SA2 = (float*)(smw + OFF_SA2);
    float* Ssc = (float*)(smw + OFF_SC);

    // ---------------- targeted halo zeroing ----------------
    // SXB: rows 0..27, word cols {0,1,2,131..135}
    for (int i = t; i < 448; i += 256) {
        int bb = (i >= 224) ? 1 : 0;
        int r = i - bb * 224;
        int row = r >> 3, w = r & 7;
        int word = (w < 3) ? w : 128 + w;
        SXB[bb * SXB_B + row * 136 + word] = 0u;
    }
    // SH1B: all pe rows, word cols {0,1,2,59,60,61}
    for (int i = t; i < 768; i += 256) {
        int bb = (i >= 384) ? 1 : 0;
        int r = i - bb * 384;
        int pe = r / 6, w = r % 6;
        int word = (w < 3) ? w : 56 + w;
        SH1B[bb * SH1B_B + pe * 72 + word] = 0u;
    }
    if (t == 0) {
        float s1 = 0.f, s2 = 0.f;
        #pragma unroll
        for (int d = 0; d < 16; ++d) { s1 += lq1[d] * lk1[d]; s2 += lq2[d] * lk2[d]; }
        Ssc[0] = __expf(s1) - __expf(s2) + LAMBDA_INIT;
    }

    // single-pass x load (2 batches), row-pair processing: full-word SXB stores
    const float* xb = x + (size_t)blockIdx.x * 2 * (A_DIM * E_DIM);
    #pragma unroll
    for (int bb = 0; bb < 2; ++bb) {
        for (int i = t; i < 28 * 64; i += 256) {
            int l0 = (i >> 6) * 2, pe = i & 63;
            const float* xrow = xb + bb * (A_DIM * E_DIM) + l0 * 128;
            float2 v0 = *(const float2*)(xrow + pe * 2);
            float2 v1 = *(const float2*)(xrow + 128 + pe * 2);
            SXE[bb * SXE_B + pe * 72 + l0]     = pack_bf2(v0.x, v0.y);
            SXE[bb * SXE_B + pe * 72 + l0 + 1] = pack_bf2(v1.x, v1.y);
            unsigned* sxb = SXB + bb * SXB_B + (l0 >> 1) * 136 + 3 + pe * 2;
            sxb[0] = pack_bf2(v0.x, v1.x);
            sxb[1] = pack_bf2(v0.y, v1.y);
        }
    }
    __syncthreads();

    // ============ conv1: D[oa 64, (b,e) 256] = Wemb x im2col(x), K=400 octet-major ======
    {
        const int mg = wid & 1, ng = wid >> 1;
        const int mbase = mg * 32;
        const int batch = ng >> 1;
        const int ebase = (ng & 1) * 64;
        const unsigned* SXBb = SXB + batch * SXB_B;
        const uint4* Wp = (const uint4*)(g_w1 + mg * (K1_STEPS * 256));

        float d[2][8][4];
        #pragma unroll
        for (int mi = 0; mi < 2; ++mi)
            #pragma unroll
            for (int ni = 0; ni < 8; ++ni)
                #pragma unroll
                for (int r = 0; r < 4; ++r) d[mi][ni][r] = 0.f;

        uint4 Q[2][2];
        #pragma unroll
        for (int s = 0; s < 2; ++s) {
            Q[s][0] = Wp[s * 64 + lane];
            Q[s][1] = Wp[s * 64 + 32 + lane];
        }

        #pragma unroll 1
        for (int ks = 0; ks < K1_STEPS; ++ks) {
            const int sb = ks & 1;
            unsigned a0[4] = { Q[sb][0].x, Q[sb][0].y, Q[sb][0].z, Q[sb][0].w };
            unsigned a1[4] = { Q[sb][1].x, Q[sb][1].y, Q[sb][1].z, Q[sb][1].w };
            if (ks + 2 < K1_STEPS) {
                Q[sb][0] = Wp[(ks + 2) * 64 + lane];
                Q[sb][1] = Wp[(ks + 2) * 64 + 32 + lane];
            }
            const int o0 = 2 * ks, o1 = 2 * ks + 1;
            const int dk0 = o0 / 7, r0 = o0 - dk0 * 7;
            int dk1 = o1 / 7, r1 = o1 - dk1 * 7;
            if (o1 >= 49) { dk1 = 0; r1 = 0; }   // zero-weight octet; safe address
            const unsigned* B0 = SXBb + (r0 * 4 + tg) * 136 + ebase + g + dk0;
            const unsigned* B1 = SXBb + (r1 * 4 + tg) * 136 + ebase + g + dk1;
            #pragma unroll
            for (int ni = 0; ni < 8; ++ni) {
                unsigned b[2] = { B0[ni * 8], B1[ni * 8] };
                mma_bf16(d[0][ni], a0, b);
                mma_bf16(d[1][ni], a1, b);
            }
        }
        // epilogue: bias + SiLU, packed bf16x2 stores into SH1B
        #pragma unroll
        for (int mi = 0; mi < 2; ++mi)
            #pragma unroll
            for (int r2 = 0; r2 < 2; ++r2) {
                int oa = mbase + mi * 16 + g + r2 * 8;
                if (oa < 56) {
                    float bias = b_emb[oa];
                    #pragma unroll
                    for (int ni = 0; ni < 8; ++ni) {
                        float v0 = silu_f(d[mi][ni][r2 * 2 + 0] + bias);
                        float v1 = silu_f(d[mi][ni][r2 * 2 + 1] + bias);
                        int pe = ((ebase + ni * 8) >> 1) + tg;
                        SH1B[batch * SH1B_B + pe * 72 + 3 + oa] = pack_bf2(v0, v1);
                    }
                }
            }
    }
    __syncthreads();

    // ============ conv2: D[oe 128, (b,a) 7x8] = Watlas x im2col(h1T), K=896 ============
    {
        const int mg = wid & 3, batch = wid >> 2;
        const int mbase = mg * 32;
        const unsigned* SHb = SH1B + batch * SH1B_B;
        const uint4* Wp = (const uint4*)(g_w2 + mg * (K2_STEPS * 256));

        float d[2][7][4];
        #pragma unroll
        for (int mi = 0; mi < 2; ++mi)
            #pragma unroll
            for (int ni = 0; ni < 7; ++ni)
                #pragma unroll
                for (int r = 0; r < 4; ++r) d[mi][ni][r] = 0.f;

        uint4 Q[2][2];
        #pragma unroll
        for (int s = 0; s < 2; ++s) {
            Q[s][0] = Wp[s * 64 + lane];
            Q[s][1] = Wp[s * 64 + 32 + lane];
        }

        #pragma unroll 1
        for (int ks = 0; ks < K2_STEPS; ++ks) {
            const int sb = ks & 1;
            unsigned a0[4] = { Q[sb][0].x, Q[sb][0].y, Q[sb][0].z, Q[sb][0].w };
            unsigned a1[4] = { Q[sb][1].x, Q[sb][1].y, Q[sb][1].z, Q[sb][1].w };
            if (ks + 2 < K2_STEPS) {
                Q[sb][0] = Wp[(ks + 2) * 64 + lane];
                Q[sb][1] = Wp[(ks + 2) * 64 + 32 + lane];
            }
            const int dk = ks >> 3;
            const int p0 = (ks & 7) * 8 + tg;
            const unsigned* B0 = SHb + p0 * 72 + g + dk;
            const unsigned* B1 = B0 + 4 * 72;
            #pragma unroll
            for (int ni = 0; ni < 7; ++ni) {
                unsigned b[2] = { B0[ni * 8], B1[ni * 8] };
                mma_bf16(d[0][ni], a0, b);
                mma_bf16(d[1][ni], a1, b);
            }
        }
        // epilogue: bias + SiLU + sum over a + quad reduce -> Sq[batch][oe]
        #pragma unroll
        for (int mi = 0; mi < 2; ++mi)
            #pragma unroll
            for (int r2 = 0; r2 < 2; ++r2) {
                int oe = mbase + mi * 16 + g + r2 * 8;
                float bias = b_atlas[oe];
                float s = 0.f;
                #pragma unroll
                for (int ni = 0; ni < 7; ++ni) {
                    s += silu_f(d[mi][ni][r2 * 2 + 0] + bias);
                    s += silu_f(d[mi][ni][r2 * 2 + 1] + bias);
                }
                s += __shfl_xor_sync(0xffffffffu, s, 1);
                s += __shfl_xor_sync(0xffffffffu, s, 2);
                if (tg == 0) Sq[batch * 128 + oe] = s;
            }
    }
    __syncthreads();

    // ============ k-proj: D[o 128, (b,l) 7x8] = Wk x x^T, K=128 (B from SXE) ============
    {
        const int mg = wid & 3, batch = wid >> 2;
        const int mbase = mg * 32;
        const unsigned* SXEb = SXE + batch * SXE_B;
        const uint4* Wp = (const uint4*)(g_w3 + mg * (K3_STEPS * 256));

        float d[2][7][4];
        #pragma unroll
        for (int mi = 0; mi < 2; ++mi)
            #pragma unroll
            for (int ni = 0; ni < 7; ++ni)
                #pragma unroll
                for (int r = 0; r < 4; ++r) d[mi][ni][r] = 0.f;

        uint4 Q[2][2];
        #pragma unroll
        for (int s = 0; s < 2; ++s) {
            Q[s][0] = Wp[s * 64 + lane];
            Q[s][1] = Wp[s * 64 + 32 + lane];
        }

        #pragma unroll 1
        for (int ks = 0; ks < K3_STEPS; ++ks) {
            const int sb = ks & 1;
            unsigned a0[4] = { Q[sb][0].x, Q[sb][0].y, Q[sb][0].z, Q[sb][0].w };
            unsigned a1[4] = { Q[sb][1].x, Q[sb][1].y, Q[sb][1].z, Q[sb][1].w };
            if (ks + 2 < K3_STEPS) {
                Q[sb][0] = Wp[(ks + 2) * 64 + lane];
                Q[sb][1] = Wp[(ks + 2) * 64 + 32 + lane];
            }
            const int p0 = ks * 8 + tg;
            const unsigned* B0 = SXEb + p0 * 72 + g;
            const unsigned* B1 = B0 + 4 * 72;
            #pragma unroll
            for (int ni = 0; ni < 7; ++ni) {
                unsigned b[2] = { B0[ni * 8], B1[ni * 8] };
                mma_bf16(d[0][ni], a0, b);
                mma_bf16(d[1][ni], a1, b);
            }
        }
        __syncthreads();   // all MMA reads done; SK overlay safe
        #pragma unroll
        for (int mi = 0; mi < 2; ++mi)
            #pragma unroll
            for (int r2 = 0; r2 < 2; ++r2) {
                int o = mbase + mi * 16 + g + r2 * 8;
                #pragma unroll
                for (int ni = 0; ni < 7; ++ni)
                    #pragma unroll
                    for (int c = 0; c < 2; ++c) {
                        int l = ni * 8 + tg * 2 + c;
                        SK[batch * SK_B + l * SK_STRIDE + o] = d[mi][ni][r2 * 2 + c];
                    }
            }
    }
    __syncthreads();

    // ================ q layernorm (Sqn overlays dead SXE) ================
    if (t < 16) {
        const int batch = t >> 3, h = t & 7;
        float qv[16];
        float m = 0.f;
        #pragma unroll
        for (int d = 0; d < 16; ++d) {
            qv[d] = Sq[batch * 128 + h * 16 + d] * (1.0f / 56.0f);
            m += qv[d];
        }
        m *= (1.0f / 16.0f);
        float var = 0.f;
        #pragma unroll
        for (int d = 0; d < 16; ++d) { float dd = qv[d] - m; var += dd * dd; }
        var *= (1.0f / 16.0f);
        float rs = rsqrtf(var + LN_EPS);
        #pragma unroll
        for (int d = 0; d < 16; ++d)
            Sqn[batch * 128 + h * 16 + d] = ((qv[d] - m) * rs * qn_w[d] + qn_b[d]) * SCALING;
    }
    __syncthreads();

    // ================ fused k-layernorm + attention logits ================
    for (int i = t; i < 896; i += 256) {
        const int batch = (i >= 448) ? 1 : 0;
        const int g2 = i - batch * 448;
        const int l = g2 >> 3, h = g2 & 7;
        const float* kp = SK + batch * SK_B + l * SK_STRIDE + h * 16;
        float kv[16];
        float m = 0.f;
        #pragma unroll
        for (int d = 0; d < 16; ++d) { kv[d] = kp[d]; m += kv[d]; }
        m *= (1.0f / 16.0f);
        float var = 0.f;
        #pragma unroll
        for (int d = 0; d < 16; ++d) { float dd = kv[d] - m; var += dd * dd; }
        var *= (1.0f / 16.0f);
        float rs = rsqrtf(var + LN_EPS);
        const float* qp = Sqn + batch * 128 + h * 16;
        float s = 0.f;
        #pragma unroll
        for (int d = 0; d < 16; ++d)
            s += ((kv[d] - m) * rs * kn_w[d] + kn_b[d]) * qp[d];
        SA[batch * 480 + h * 60 + l] = s;
    }
    __syncthreads();

    // ================ double softmax + output ================
    if (t < 16) {
        const int batch = t >> 3, h = t & 7;
        float* row = SA + batch * 480 + h * 60;
        float mx = -1e30f;
        for (int l = 0; l < 56; ++l) mx = fmaxf(mx, row[l]);
        float sum = 0.f;
        for (int l = 0; l < 56; ++l) { float e = __expf(row[l] - mx); row[l] = e; sum += e; }
        float inv = 1.0f / sum;
        for (int l = 0; l < 56; ++l) row[l] *= inv;
    }
    __syncthreads();
    if (t < 8) {
        const int batch = t >> 2, hh = t & 3;
        const float lam = Ssc[0];
        const float* p0 = SA + batch * 480 + (2 * hh) * 60;
        const float* p1 = SA + batch * 480 + (2 * hh + 1) * 60;
        float* dst = SA2 + batch * 240 + hh * 60;
        float mx = -1e30f;
        for (int l = 0; l < 56; ++l) {
            float v = p0[l] - lam * p1[l];
            dst[l] = v;
            mx = fmaxf(mx, v);
        }
        float sum = 0.f;
        for (int l = 0; l < 56; ++l) { float e = __expf(dst[l] - mx); dst[l] = e; sum += e; }
        float inv = 1.0f / sum;
        for (int l = 0; l < 56; ++l) dst[l] *= inv;
    }
    __syncthreads();
    if (t < 112) {
        const int batch = (t >= 56) ? 1 : 0;
        const int l = t - batch * 56;
        const float* base = SA2 + batch * 240;
        out[((size_t)blockIdx.x * 2 + batch) * 56 + l] =
            0.25f * (base[l] + base[60 + l] + base[120 + l] + base[180 + l]);
    }
}

extern "C" void kernel_launch(void* const* d_in, const int* in_sizes, int n_in,
                              void* d_out, int out_size) {
    const float* x       = (const float*)d_in[0];
    const float* w_emb   = (const float*)d_in[1];
    const float* b_emb   = (const float*)d_in[2];
    const float* w_atlas = (const float*)d_in[3];
    const float* b_atlas = (const float*)d_in[4];
    const float* w_k     = (const float*)d_in[5];
    const float* qn_w    = (const float*)d_in[6];
    const float* qn_b    = (const float*)d_in[7];
    const float* kn_w    = (const float*)d_in[8];
    const float* kn_b    = (const float*)d_in[9];
    const float* lq1     = (const float*)d_in[10];
    const float* lk1     = (const float*)d_in[11];
    const float* lq2     = (const float*)d_in[12];
    const float* lk2     = (const float*)d_in[13];
    float* out = (float*)d_out;

    const int B = in_sizes[0] / (A_DIM * E_DIM);

    repack_kernel<<<(W_TOTAL + 255) / 256, 256>>>(w_emb, w_atlas, w_k);

    const size_t smem = SMEM_WORDS * sizeof(unsigned);
    cudaFuncSetAttribute(atlas_mdattn_tc,
                         cudaFuncAttributeMaxDynamicSharedMemorySize, (int)smem);
    atlas_mdattn_tc<<<B / 2, 256, smem>>>(
        x, b_emb, b_atlas,
        qn_w, qn_b, kn_w, kn_b, lq1, lk1, lq2, lk2, out);
}

// round 17
// speedup vs baseline: 1.0605x; 1.0605x over previous
#include <cuda_runtime.h>
#include <cuda_bf16.h>
#include <math.h>

// ---- problem constants ----
#define A_DIM 56
#define E_DIM 128
#define LAMBDA_INIT 0.7f
#define LN_EPS 1e-5f
#define SCALING 0.25f   // HD^-0.5, HD=16

// ---- repacked weight sizes (32-bit words, each = bf16x2) ----
#define K1_STEPS 25               // conv1: K = 400 (49 octets + 1 zero octet), /16
#define K2_STEPS 56               // conv2: K = 7*128=896, /16
#define K3_STEPS 8                // kproj: K=128, /16
#define W1_WORDS (2 * K1_STEPS * 256)
#define W2_WORDS (4 * K2_STEPS * 256)
#define W3_WORDS (4 * K3_STEPS * 256)
#define W_TOTAL  (W1_WORDS + W2_WORDS + W3_WORDS)

__device__ __align__(16) unsigned g_w1[W1_WORDS];
__device__ __align__(16) unsigned g_w2[W2_WORDS];
__device__ __align__(16) unsigned g_w3[W3_WORDS];

// ---- smem layout (32-bit words), TWO batches per CTA, 2 CTAs/SM ----
#define SXE_B   4608
#define SXB_B   4352
#define SH1B_B  4608
#define SK_B    7680              // [128 o][60] f32, transposed
#define SK_STRIDE 60

#define OFF_SXE   0
#define OFF_SXB   9216
#define OFF_SH1B  17920
#define OFF_SK    9216            // overlay SXB+SH1B (2*7680 = 15360 <= 17920)
#define OFF_SQ    27136           // [2][128] f32
#define OFF_SC    27392
#define OFF_SQN   0               // overlay SXE (dead after kproj)
#define OFF_SA    256
#define OFF_SA2   1216
#define SMEM_WORDS 27396          // 109584 B -> 2 CTAs/SM

__device__ __forceinline__ float silu_f(float v) {
    return v / (1.0f + __expf(-v));
}
__device__ __forceinline__ unsigned pack_bf2(float lo, float hi) {
    unsigned u;
    asm("cvt.rn.bf16x2.f32 %0, %1, %2;" : "=r"(u) : "f"(hi), "f"(lo));
    return u;
}
__device__ __forceinline__ void mma_bf16(float* d, const unsigned* a, const unsigned* b) {
    asm volatile(
        "mma.sync.aligned.m16n8k16.row.col.f32.bf16.bf16.f32 "
        "{%0,%1,%2,%3}, {%4,%5,%6,%7}, {%8,%9}, {%0,%1,%2,%3};"
        : "+f"(d[0]), "+f"(d[1]), "+f"(d[2]), "+f"(d[3])
        : "r"(a[0]), "r"(a[1]), "r"(a[2]), "r"(a[3]), "r"(b[0]), "r"(b[1]));
}

// ================== weight repack: fragment-order bf16x2 (R15 layout) ==================
// word idx per m-group block = ks*256 + j2*64 + lane*2 + p; j = 2*j2+p, r = j&3,
// row = mg*32 + (j>>2)*16 + g + (r&1)*8 ; kk0 = ks*16 + 2*tg + (r>=2)*8.
// conv1: OCTET-major k: kk -> o=kk>>3, w=kk&7; ia=(o%7)*8+w, dk=o/7; valid o<49
// conv2: tap-major: kk -> dk=kk>>7, ie=kk&127
// kproj: kk = e
__global__ void __launch_bounds__(256)
repack_kernel(const float* __restrict__ w_emb,
              const float* __restrict__ w_atlas,
              const float* __restrict__ w_k)
{
    int i = blockIdx.x * 256 + threadIdx.x;
    if (i >= W_TOTAL) return;

    const float* src;
    unsigned* dst;
    int K, src_stride, row_lim, ii, which;
    if (i < W1_WORDS) {
        ii = i; src = w_emb; dst = g_w1; K = K1_STEPS; src_stride = 392; row_lim = 56; which = 1;
    } else if (i < W1_WORDS + W2_WORDS) {
        ii = i - W1_WORDS; src = w_atlas; dst = g_w2; K = K2_STEPS; src_stride = 896; row_lim = 128; which = 2;
    } else {
        ii = i - W1_WORDS - W2_WORDS; src = w_k; dst = g_w3; K = K3_STEPS; src_stride = 128; row_lim = 128; which = 3;
    }
    int p    = ii & 1;
    int lane = (ii >> 1) & 31;
    int j2   = (ii >> 6) & 3;
    int blk  = ii >> 8;
    int ks   = blk % K;
    int mg   = blk / K;
    int j    = j2 * 2 + p;
    int r    = j & 3;
    int g = lane >> 2, tg = lane & 3;
    int row = mg * 32 + (j >> 2) * 16 + g + ((r & 1) ? 8 : 0);
    int kk0 = ks * 16 + 2 * tg + ((r >= 2) ? 8 : 0);

    float v[2] = {0.f, 0.f};
    if (row < row_lim) {
        #pragma unroll
        for (int c = 0; c < 2; ++c) {
            int kk = kk0 + c;
            int col = -1;
            if (which == 1) {
                int o = kk >> 3, w = kk & 7;
                if (o < 49) {
                    int ia = (o % 7) * 8 + w, dk = o / 7;
                    col = ia * 7 + dk;
                }
            } else if (which == 2) {
                int dk = kk >> 7, ie = kk & 127;
                col = ie * 7 + dk;
            } else {
                col = kk;
            }
            if (col >= 0) v[c] = src[row * src_stride + col];
        }
    }
    dst[ii] = pack_bf2(v[0], v[1]);
}

extern __shared__ unsigned smw[];

__global__ void __launch_bounds__(256, 2)
atlas_mdattn_tc(
    const float* __restrict__ x,       // [B,56,128]
    const float* __restrict__ b_emb,   // [56]
    const float* __restrict__ b_atlas, // [128]
    const float* __restrict__ qn_w, const float* __restrict__ qn_b,
    const float* __restrict__ kn_w, const float* __restrict__ kn_b,
    const float* __restrict__ lq1, const float* __restrict__ lk1,
    const float* __restrict__ lq2, const float* __restrict__ lk2,
    float* __restrict__ out)           // [B,56]
{
    const int t = threadIdx.x;
    const int lane = t & 31, wid = t >> 5;
    const int g = lane >> 2, tg = lane & 3;

    char* smb = (char*)smw;
    unsigned* SXE  = smw + OFF_SXE;
    unsigned* SXB  = smw + OFF_SXB;
    unsigned* SH1B = smw + OFF_SH1B;
    float* SK  = (float*)(smw + OFF_SK);
    float* Sq  = (float*)(smw + OFF_SQ);
    float* Sqn = (float*)(smw + OFF_SQN);
    float* SA  = (float*)(smw + OFF_SA);
    float* SA2 = (float*)(smw + OFF_SA2);
    float* Ssc = (float*)(smw + OFF_SC);

    // ---------------- targeted halo zeroing ----------------
    // SXB: rows 0..27, word cols {0,1,2,131..135}
    for (int i = t; i < 448; i += 256) {
        int bb = (i >= 224) ? 1 : 0;
        int r = i - bb * 224;
        int row = r >> 3, w = r & 7;
        int word = (w < 3) ? w : 128 + w;
        SXB[bb * SXB_B + row * 136 + word] = 0u;
    }
    // SH1B: all pe rows, word cols {0,1,2,59,60,61}
    for (int i = t; i < 768; i += 256) {
        int bb = (i >= 384) ? 1 : 0;
        int r = i - bb * 384;
        int pe = r / 6, w = r % 6;
        int word = (w < 3) ? w : 56 + w;
        SH1B[bb * SH1B_B + pe * 72 + word] = 0u;
    }
    if (t == 0) {
        float s1 = 0.f, s2 = 0.f;
        #pragma unroll
        for (int d = 0; d < 16; ++d) { s1 += lq1[d] * lk1[d]; s2 += lq2[d] * lk2[d]; }
        Ssc[0] = __expf(s1) - __expf(s2) + LAMBDA_INIT;
    }

    // single-pass x load (2 batches): one float2 read feeds SXE (packed) + SXB (2x 16-bit)
    const float* xb = x + (size_t)blockIdx.x * 2 * (A_DIM * E_DIM);
    #pragma unroll
    for (int bb = 0; bb < 2; ++bb) {
        for (int i = t; i < A_DIM * 64; i += 256) {
            int l = i >> 6, pe = i & 63;
            float2 v = *(const float2*)(xb + bb * (A_DIM * E_DIM) + l * 128 + pe * 2);
            SXE[bb * SXE_B + pe * 72 + l] = pack_bf2(v.x, v.y);
            unsigned base = (unsigned)(((OFF_SXB + bb * SXB_B) + (l >> 1) * 136 + 3 + pe * 2) << 2) + ((l & 1) << 1);
            *(__nv_bfloat16*)(smb + base)     = __float2bfloat16(v.x);
            *(__nv_bfloat16*)(smb + base + 4) = __float2bfloat16(v.y);
        }
    }
    __syncthreads();

    // ============ conv1: D[oa 64, (b,e) 256] = Wemb x im2col(x), K=400 octet-major ======
    {
        const int mg = wid & 1, ng = wid >> 1;
        const int mbase = mg * 32;
        const int batch = ng >> 1;
        const int ebase = (ng & 1) * 64;
        const unsigned* SXBb = SXB + batch * SXB_B;
        const uint2* Wp = (const uint2*)(g_w1 + mg * (K1_STEPS * 256));

        float d[2][8][4];
        #pragma unroll
        for (int mi = 0; mi < 2; ++mi)
            #pragma unroll
            for (int ni = 0; ni < 8; ++ni)
                #pragma unroll
                for (int r = 0; r < 4; ++r) d[mi][ni][r] = 0.f;

        uint2 P[2][4];
        #pragma unroll
        for (int s = 0; s < 2; ++s)
            #pragma unroll
            for (int j2 = 0; j2 < 4; ++j2)
                P[s][j2] = Wp[s * 128 + j2 * 32 + lane];

        #pragma unroll 1
        for (int ks = 0; ks < K1_STEPS; ++ks) {
            const int sb = ks & 1;
            unsigned a0[4] = { P[sb][0].x, P[sb][0].y, P[sb][1].x, P[sb][1].y };
            unsigned a1[4] = { P[sb][2].x, P[sb][2].y, P[sb][3].x, P[sb][3].y };
            if (ks + 2 < K1_STEPS) {
                #pragma unroll
                for (int j2 = 0; j2 < 4; ++j2)
                    P[sb][j2] = Wp[(ks + 2) * 128 + j2 * 32 + lane];
            }
            const int o0 = 2 * ks, o1 = 2 * ks + 1;
            const int dk0 = o0 / 7, r0 = o0 - dk0 * 7;
            int dk1 = o1 / 7, r1 = o1 - dk1 * 7;
            if (o1 >= 49) { dk1 = 0; r1 = 0; }   // zero-weight octet; safe address
            const unsigned* B0 = SXBb + (r0 * 4 + tg) * 136 + ebase + g + dk0;
            const unsigned* B1 = SXBb + (r1 * 4 + tg) * 136 + ebase + g + dk1;
            #pragma unroll
            for (int ni = 0; ni < 8; ++ni) {
                unsigned b[2] = { B0[ni * 8], B1[ni * 8] };
                mma_bf16(d[0][ni], a0, b);
                mma_bf16(d[1][ni], a1, b);
            }
        }
        // epilogue: bias + SiLU, packed bf16x2 stores into SH1B
        #pragma unroll
        for (int mi = 0; mi < 2; ++mi)
            #pragma unroll
            for (int r2 = 0; r2 < 2; ++r2) {
                int oa = mbase + mi * 16 + g + r2 * 8;
                if (oa < 56) {
                    float bias = b_emb[oa];
                    #pragma unroll
                    for (int ni = 0; ni < 8; ++ni) {
                        float v0 = silu_f(d[mi][ni][r2 * 2 + 0] + bias);
                        float v1 = silu_f(d[mi][ni][r2 * 2 + 1] + bias);
                        int pe = ((ebase + ni * 8) >> 1) + tg;
                        SH1B[batch * SH1B_B + pe * 72 + 3 + oa] = pack_bf2(v0, v1);
                    }
                }
            }
    }
    __syncthreads();

    // ============ conv2: D[oe 128, (b,a) 7x8] = Watlas x im2col(h1T), K=896 ============
    {
        const int mg = wid & 3, batch = wid >> 2;
        const int mbase = mg * 32;
        const unsigned* SHb = SH1B + batch * SH1B_B;
        const uint2* Wp = (const uint2*)(g_w2 + mg * (K2_STEPS * 256));

        float d[2][7][4];
        #pragma unroll
        for (int mi = 0; mi < 2; ++mi)
            #pragma unroll
            for (int ni = 0; ni < 7; ++ni)
                #pragma unroll
                for (int r = 0; r < 4; ++r) d[mi][ni][r] = 0.f;

        uint2 P[2][4];
        #pragma unroll
        for (int s = 0; s < 2; ++s)
            #pragma unroll
            for (int j2 = 0; j2 < 4; ++j2)
                P[s][j2] = Wp[s * 128 + j2 * 32 + lane];

        #pragma unroll 1
        for (int ks = 0; ks < K2_STEPS; ++ks) {
            const int sb = ks & 1;
            unsigned a0[4] = { P[sb][0].x, P[sb][0].y, P[sb][1].x, P[sb][1].y };
            unsigned a1[4] = { P[sb][2].x, P[sb][2].y, P[sb][3].x, P[sb][3].y };
            if (ks + 2 < K2_STEPS) {
                #pragma unroll
                for (int j2 = 0; j2 < 4; ++j2)
                    P[sb][j2] = Wp[(ks + 2) * 128 + j2 * 32 + lane];
            }
            const int dk = ks >> 3;
            const int p0 = (ks & 7) * 8 + tg;
            const unsigned* B0 = SHb + p0 * 72 + g + dk;
            const unsigned* B1 = B0 + 4 * 72;
            #pragma unroll
            for (int ni = 0; ni < 7; ++ni) {
                unsigned b[2] = { B0[ni * 8], B1[ni * 8] };
                mma_bf16(d[0][ni], a0, b);
                mma_bf16(d[1][ni], a1, b);
            }
        }
        // epilogue: bias + SiLU + sum over a + quad reduce -> Sq[batch][oe]
        #pragma unroll
        for (int mi = 0; mi < 2; ++mi)
            #pragma unroll
            for (int r2 = 0; r2 < 2; ++r2) {
                int oe = mbase + mi * 16 + g + r2 * 8;
                float bias = b_atlas[oe];
                float s = 0.f;
                #pragma unroll
                for (int ni = 0; ni < 7; ++ni) {
                    s += silu_f(d[mi][ni][r2 * 2 + 0] + bias);
                    s += silu_f(d[mi][ni][r2 * 2 + 1] + bias);
                }
                s += __shfl_xor_sync(0xffffffffu, s, 1);
                s += __shfl_xor_sync(0xffffffffu, s, 2);
                if (tg == 0) Sq[batch * 128 + oe] = s;
            }
    }
    __syncthreads();

    // ============ k-proj: D[o 128, (b,l) 7x8] = Wk x x^T, K=128 (B from SXE) ============
    {
        const int mg = wid & 3, batch = wid >> 2;
        const int mbase = mg * 32;
        const unsigned* SXEb = SXE + batch * SXE_B;
        const uint2* Wp = (const uint2*)(g_w3 + mg * (K3_STEPS * 256));

        float d[2][7][4];
        #pragma unroll
        for (int mi = 0; mi < 2; ++mi)
            #pragma unroll
            for (int ni = 0; ni < 7; ++ni)
                #pragma unroll
                for (int r = 0; r < 4; ++r) d[mi][ni][r] = 0.f;

        uint2 P[2][4];
        #pragma unroll
        for (int s = 0; s < 2; ++s)
            #pragma unroll
            for (int j2 = 0; j2 < 4; ++j2)
                P[s][j2] = Wp[s * 128 + j2 * 32 + lane];

        #pragma unroll 1
        for (int ks = 0; ks < K3_STEPS; ++ks) {
            const int sb = ks & 1;
            unsigned a0[4] = { P[sb][0].x, P[sb][0].y, P[sb][1].x, P[sb][1].y };
            unsigned a1[4] = { P[sb][2].x, P[sb][2].y, P[sb][3].x, P[sb][3].y };
            if (ks + 2 < K3_STEPS) {
                #pragma unroll
                for (int j2 = 0; j2 < 4; ++j2)
                    P[sb][j2] = Wp[(ks + 2) * 128 + j2 * 32 + lane];
            }
            const int p0 = ks * 8 + tg;
            const unsigned* B0 = SXEb + p0 * 72 + g;
            const unsigned* B1 = B0 + 4 * 72;
            #pragma unroll
            for (int ni = 0; ni < 7; ++ni) {
                unsigned b[2] = { B0[ni * 8], B1[ni * 8] };
                mma_bf16(d[0][ni], a0, b);
                mma_bf16(d[1][ni], a1, b);
            }
        }
        __syncthreads();   // all MMA reads done; SK overlay safe
        // store K TRANSPOSED: SK[o][l], stride 60
        #pragma unroll
        for (int mi = 0; mi < 2; ++mi)
            #pragma unroll
            for (int r2 = 0; r2 < 2; ++r2) {
                int o = mbase + mi * 16 + g + r2 * 8;
                #pragma unroll
                for (int ni = 0; ni < 7; ++ni)
                    #pragma unroll
                    for (int c = 0; c < 2; ++c) {
                        int l = ni * 8 + tg * 2 + c;
                        SK[batch * SK_B + o * SK_STRIDE + l] = d[mi][ni][r2 * 2 + c];
                    }
            }
    }
    __syncthreads();

    // ================ q layernorm (Sqn overlays dead SXE) ================
    if (t < 16) {
        const int batch = t >> 3, h = t & 7;
        float qv[16];
        float m = 0.f;
        #pragma unroll
        for (int d = 0; d < 16; ++d) {
            qv[d] = Sq[batch * 128 + h * 16 + d] * (1.0f / 56.0f);
            m += qv[d];
        }
        m *= (1.0f / 16.0f);
        float var = 0.f;
        #pragma unroll
        for (int d = 0; d < 16; ++d) { float dd = qv[d] - m; var += dd * dd; }
        var *= (1.0f / 16.0f);
        float rs = rsqrtf(var + LN_EPS);
        #pragma unroll
        for (int d = 0; d < 16; ++d)
            Sqn[batch * 128 + h * 16 + d] = ((qv[d] - m) * rs * qn_w[d] + qn_b[d]) * SCALING;
    }
    __syncthreads();

    // ================ fused k-layernorm + attention logits (l-major, conflict-free) ======
    for (int i = t; i < 896; i += 256) {
        const int batch = (i >= 448) ? 1 : 0;
        const int r = i - batch * 448;
        const int l = r % 56, h = r / 56;
        const float* kp = SK + batch * SK_B + (h * 16) * SK_STRIDE + l;
        float kv[16];
        float m = 0.f;
        #pragma unroll
        for (int d = 0; d < 16; ++d) { kv[d] = kp[d * SK_STRIDE]; m += kv[d]; }
        m *= (1.0f / 16.0f);
        float var = 0.f;
        #pragma unroll
        for (int d = 0; d < 16; ++d) { float dd = kv[d] - m; var += dd * dd; }
        var *= (1.0f / 16.0f);
        float rs = rsqrtf(var + LN_EPS);
        const float* qp = Sqn + batch * 128 + h * 16;
        float s = 0.f;
        #pragma unroll
        for (int d = 0; d < 16; ++d)
            s += ((kv[d] - m) * rs * kn_w[d] + kn_b[d]) * qp[d];
        SA[batch * 480 + h * 60 + l] = s;
    }
    __syncthreads();

    // ================ double softmax + output ================
    if (t < 16) {
        const int batch = t >> 3, h = t & 7;
        float* row = SA + batch * 480 + h * 60;
        float mx = -1e30f;
        for (int l = 0; l < 56; ++l) mx = fmaxf(mx, row[l]);
        float sum = 0.f;
        for (int l = 0; l < 56; ++l) { float e = __expf(row[l] - mx); row[l] = e; sum += e; }
        float inv = 1.0f / sum;
        for (int l = 0; l < 56; ++l) row[l] *= inv;
    }
    __syncthreads();
    if (t < 8) {
        const int batch = t >> 2, hh = t & 3;
        const float lam = Ssc[0];
        const float* p0 = SA + batch * 480 + (2 * hh) * 60;
        const float* p1 = SA + batch * 480 + (2 * hh + 1) * 60;
        float* dst = SA2 + batch * 240 + hh * 60;
        float mx = -1e30f;
        for (int l = 0; l < 56; ++l) {
            float v = p0[l] - lam * p1[l];
            dst[l] = v;
            mx = fmaxf(mx, v);
        }
        float sum = 0.f;
        for (int l = 0; l < 56; ++l) { float e = __expf(dst[l] - mx); dst[l] = e; sum += e; }
        float inv = 1.0f / sum;
        for (int l = 0; l < 56; ++l) dst[l] *= inv;
    }
    __syncthreads();
    if (t < 112) {
        const int batch = (t >= 56) ? 1 : 0;
        const int l = t - batch * 56;
        const float* base = SA2 + batch * 240;
        out[((size_t)blockIdx.x * 2 + batch) * 56 + l] =
            0.25f * (base[l] + base[60 + l] + base[120 + l] + base[180 + l]);
    }
}

extern "C" void kernel_launch(void* const* d_in, const int* in_sizes, int n_in,
                              void* d_out, int out_size) {
    const float* x       = (const float*)d_in[0];
    const float* w_emb   = (const float*)d_in[1];
    const float* b_emb   = (const float*)d_in[2];
    const float* w_atlas = (const float*)d_in[3];
    const float* b_atlas = (const float*)d_in[4];
    const float* w_k     = (const float*)d_in[5];
    const float* qn_w    = (const float*)d_in[6];
    const float* qn_b    = (const float*)d_in[7];
    const float* kn_w    = (const float*)d_in[8];
    const float* kn_b    = (const float*)d_in[9];
    const float* lq1     = (const float*)d_in[10];
    const float* lk1     = (const float*)d_in[11];
    const float* lq2     = (const float*)d_in[12];
    const float* lk2     = (const float*)d_in[13];
    float* out = (float*)d_out;

    const int B = in_sizes[0] / (A_DIM * E_DIM);

    repack_kernel<<<(W_TOTAL + 255) / 256, 256>>>(w_emb, w_atlas, w_k);

    const size_t smem = SMEM_WORDS * sizeof(unsigned);
    cudaFuncSetAttribute(atlas_mdattn_tc,
                         cudaFuncAttributeMaxDynamicSharedMemorySize, (int)smem);
    atlas_mdattn_tc<<<B / 2, 256, smem>>>(
        x, b_emb, b_atlas,
        qn_w, qn_b, kn_w, kn_b, lq1, lk1, lq2, lk2, out);
}